// round 1
// baseline (speedup 1.0000x reference)
#include <cuda_runtime.h>
#include <stdint.h>

#define D 128
#define E_CAP 16384
#define N_CAP 65536
#define EPS 1e-8f

// ---------------- scratch (static device globals; no allocation) ------------
__device__ float g_xnode[(size_t)N_CAP * D];     // 33.5 MB
__device__ float g_edgesum[(size_t)E_CAP * D];   // 8.4 MB
__device__ float g_cnt[E_CAP];
__device__ float g_deg[N_CAP];
__device__ int   g_is64;

// ---------------- utility: zero a float4 range ------------------------------
__global__ void zero4_kernel(float4* __restrict__ p, int n4) {
    int i = blockIdx.x * blockDim.x + threadIdx.x;
    if (i < n4) p[i] = make_float4(0.f, 0.f, 0.f, 0.f);
}

// ---------------- index dtype detection (int64 vs int32) --------------------
// int64 little-endian values < 2^31 -> odd int32 words are zero.
__global__ void detect_kernel(const int* __restrict__ h) {
    if (blockIdx.x == 0 && threadIdx.x == 0) {
        g_is64 = (h[1] == 0 && h[3] == 0 && h[5] == 0 && h[7] == 0) ? 1 : 0;
    }
}

__device__ __forceinline__ void load_pair(const void* base, int gw, int nnz,
                                          int& src, int& e) {
    if (g_is64) {
        const long long* p = (const long long*)base;
        src = (int)p[gw];
        e   = (int)p[nnz + gw];
    } else {
        const int* p = (const int*)base;
        src = p[gw];
        e   = p[nnz + gw];
    }
}

__device__ __forceinline__ void red_add_v4(float* dst, float4 v) {
    asm volatile("red.global.add.v4.f32 [%0], {%1, %2, %3, %4};"
                 :: "l"(dst), "f"(v.x), "f"(v.y), "f"(v.z), "f"(v.w)
                 : "memory");
}

// ---------------- GEMM: g_xnode = x @ W^T -----------------------------------
// Block: 64 rows x 128 cols. 256 threads, each computes 4 rows x 8 cols.
#define WT_STRIDE 132
#define GEMM_SMEM ((128 * WT_STRIDE + 64 * WT_STRIDE) * 4)

__global__ __launch_bounds__(256) void gemm_kernel(const float* __restrict__ x,
                                                   const float* __restrict__ W,
                                                   int N) {
    extern __shared__ float sm[];
    float* WT = sm;                       // [128][132], WT[k][j] = W[j][k]
    float* Xs = sm + 128 * WT_STRIDE;     // [64][132]

    int t = threadIdx.x;
    int row0 = blockIdx.x * 64;

    #pragma unroll
    for (int i = 0; i < 64; i++) {
        int idx = t + i * 256;
        int j = idx >> 7, k = idx & 127;
        WT[k * WT_STRIDE + j] = W[idx];
    }
    #pragma unroll
    for (int i = 0; i < 32; i++) {
        int idx = t + i * 256;
        int r = idx >> 7, k = idx & 127;
        int row = row0 + r;
        if (row >= N) row = N - 1;
        Xs[r * WT_STRIDE + k] = x[(size_t)row * D + k];
    }
    __syncthreads();

    int tx = t & 15, ty = t >> 4;
    int c0 = tx * 8, r0 = ty * 4;

    float acc[4][8];
    #pragma unroll
    for (int i = 0; i < 4; i++)
        #pragma unroll
        for (int j = 0; j < 8; j++) acc[i][j] = 0.f;

    #pragma unroll 4
    for (int k = 0; k < 128; k++) {
        float4 w0 = *(const float4*)(WT + k * WT_STRIDE + c0);
        float4 w1 = *(const float4*)(WT + k * WT_STRIDE + c0 + 4);
        #pragma unroll
        for (int i = 0; i < 4; i++) {
            float a = Xs[(r0 + i) * WT_STRIDE + k];
            acc[i][0] += a * w0.x; acc[i][1] += a * w0.y;
            acc[i][2] += a * w0.z; acc[i][3] += a * w0.w;
            acc[i][4] += a * w1.x; acc[i][5] += a * w1.y;
            acc[i][6] += a * w1.z; acc[i][7] += a * w1.w;
        }
    }

    #pragma unroll
    for (int i = 0; i < 4; i++) {
        int row = row0 + r0 + i;
        if (row < N) {
            float4 o0 = make_float4(acc[i][0], acc[i][1], acc[i][2], acc[i][3]);
            float4 o1 = make_float4(acc[i][4], acc[i][5], acc[i][6], acc[i][7]);
            *(float4*)(g_xnode + (size_t)row * D + c0)     = o0;
            *(float4*)(g_xnode + (size_t)row * D + c0 + 4) = o1;
        }
    }
}

// ---------------- phase A: node -> edge scatter ------------------------------
// One warp per nnz entry: gather x_node[src] (float4/lane), RED into edge_sum.
__global__ __launch_bounds__(256) void scatter_edge_kernel(const void* __restrict__ base,
                                                           int nnz) {
    int gw = (blockIdx.x * blockDim.x + threadIdx.x) >> 5;
    int lane = threadIdx.x & 31;
    if (gw >= nnz) return;
    int src, e;
    load_pair(base, gw, nnz, src, e);
    float4 v = *(const float4*)(g_xnode + (size_t)src * D + lane * 4);
    red_add_v4(g_edgesum + (size_t)e * D + lane * 4, v);
    if (lane == 0) atomicAdd(&g_cnt[e], 1.0f);
}

// ---------------- phase B: edge -> node scatter (normalization fused) -------
__global__ __launch_bounds__(256) void scatter_node_kernel(const void* __restrict__ base,
                                                           float* __restrict__ out,
                                                           int nnz) {
    int gw = (blockIdx.x * blockDim.x + threadIdx.x) >> 5;
    int lane = threadIdx.x & 31;
    if (gw >= nnz) return;
    int src, e;
    load_pair(base, gw, nnz, src, e);
    float s = 1.0f / (g_cnt[e] + EPS);
    float4 v = *(const float4*)(g_edgesum + (size_t)e * D + lane * 4);
    v.x *= s; v.y *= s; v.z *= s; v.w *= s;
    red_add_v4(out + (size_t)src * D + lane * 4, v);
    if (lane == 0) atomicAdd(&g_deg[src], 1.0f);
}

// ---------------- finalize: out = out/(deg+eps) + x_node + bias -------------
__global__ __launch_bounds__(256) void finalize_kernel(float* __restrict__ out,
                                                       const float* __restrict__ bias,
                                                       int N) {
    int idx = blockIdx.x * blockDim.x + threadIdx.x;  // one float4 each
    int total = N * (D / 4);
    if (idx >= total) return;
    int n = idx >> 5;   // D/4 = 32 float4 per row
    int l = idx & 31;
    float s = 1.0f / (g_deg[n] + EPS);
    float4 o  = ((float4*)out)[idx];
    float4 xn = ((const float4*)g_xnode)[(size_t)n * 32 + l];
    float4 b  = ((const float4*)bias)[l];
    o.x = o.x * s + xn.x + b.x;
    o.y = o.y * s + xn.y + b.y;
    o.z = o.z * s + xn.z + b.z;
    o.w = o.w * s + xn.w + b.w;
    ((float4*)out)[idx] = o;
}

// ---------------- launch -----------------------------------------------------
extern "C" void kernel_launch(void* const* d_in, const int* in_sizes, int n_in,
                              void* d_out, int out_size) {
    const float* x    = (const float*)d_in[0];
    const void*  hidx = d_in[1];
    const float* W    = (const float*)d_in[2];
    const float* bias = (const float*)d_in[3];
    float* out = (float*)d_out;

    int N   = in_sizes[0] / D;
    int nnz = in_sizes[1] / 2;

    void* p_es;  cudaGetSymbolAddress(&p_es,  g_edgesum);
    void* p_cnt; cudaGetSymbolAddress(&p_cnt, g_cnt);
    void* p_deg; cudaGetSymbolAddress(&p_deg, g_deg);

    // zero scratch + output accumulator
    {
        int n4 = (E_CAP * D) / 4;
        zero4_kernel<<<(n4 + 255) / 256, 256>>>((float4*)p_es, n4);
        n4 = E_CAP / 4;
        zero4_kernel<<<(n4 + 255) / 256, 256>>>((float4*)p_cnt, n4);
        n4 = N_CAP / 4;
        zero4_kernel<<<(n4 + 255) / 256, 256>>>((float4*)p_deg, n4);
        n4 = N * (D / 4);
        zero4_kernel<<<(n4 + 255) / 256, 256>>>((float4*)out, n4);
    }

    detect_kernel<<<1, 32>>>((const int*)hidx);

    cudaFuncSetAttribute(gemm_kernel,
                         cudaFuncAttributeMaxDynamicSharedMemorySize, GEMM_SMEM);
    gemm_kernel<<<(N + 63) / 64, 256, GEMM_SMEM>>>(x, W, N);

    int blocks = (nnz + 7) / 8;  // 8 warps/block, 1 warp per entry
    scatter_edge_kernel<<<blocks, 256>>>(hidx, nnz);
    scatter_node_kernel<<<blocks, 256>>>(hidx, out, nnz);

    int totf4 = N * (D / 4);
    finalize_kernel<<<(totf4 + 255) / 256, 256>>>(out, bias, N);
}

// round 2
// speedup vs baseline: 1.2328x; 1.2328x over previous
#include <cuda_runtime.h>
#include <stdint.h>

#define D 128
#define E_CAP 16384
#define N_CAP 65536
#define NNZ_CAP (1 << 20)
#define EPS 1e-8f

// ---------------- scratch (static device globals; no allocation) ------------
__device__ float g_xnode[(size_t)N_CAP * D];      // 33.5 MB
__device__ float g_heattr[(size_t)E_CAP * D];     // 8.4 MB
__device__ int   g_eidx[NNZ_CAP];                 // node id per edge-CSR slot
__device__ int   g_nidx[NNZ_CAP];                 // edge id per node-CSR slot
__device__ int   g_eoff[E_CAP + 1];
__device__ int   g_noff[N_CAP + 1];
__device__ int   g_cnts[2 * (E_CAP + N_CAP)];     // ecnt | ncnt | ecur | ncur
__device__ int   g_is64;

#define ECNT (g_cnts)
#define NCNT (g_cnts + E_CAP)
#define ECUR (g_cnts + E_CAP + N_CAP)
#define NCUR (g_cnts + E_CAP + N_CAP + E_CAP)

// ---------------- zero counters ----------------------------------------------
__global__ void zero_cnts_kernel() {
    int i = blockIdx.x * blockDim.x + threadIdx.x;
    ((int4*)g_cnts)[i] = make_int4(0, 0, 0, 0);
}

// ---------------- index dtype detection (int64 vs int32) --------------------
__global__ void detect_kernel(const int* __restrict__ h) {
    if (threadIdx.x == 0) {
        g_is64 = (h[1] == 0 && h[3] == 0 && h[5] == 0 && h[7] == 0) ? 1 : 0;
    }
}

__device__ __forceinline__ void load_pair(const void* base, int i, int nnz,
                                          int& src, int& e) {
    if (g_is64) {
        const long long* p = (const long long*)base;
        src = (int)p[i];
        e   = (int)p[nnz + i];
    } else {
        const int* p = (const int*)base;
        src = p[i];
        e   = p[nnz + i];
    }
}

// ---------------- CSR build: histogram ---------------------------------------
__global__ __launch_bounds__(256) void hist_kernel(const void* __restrict__ base, int nnz) {
    int i = blockIdx.x * blockDim.x + threadIdx.x;
    if (i >= nnz) return;
    int src, e;
    load_pair(base, i, nnz, src, e);
    atomicAdd(&ECNT[e], 1);
    atomicAdd(&NCNT[src], 1);
}

// ---------------- CSR build: exclusive scan (block 0: edges, block 1: nodes) -
#define SCAN_THREADS 1024
__global__ __launch_bounds__(SCAN_THREADS) void scan_kernel() {
    int* cnt; int* off; int n;
    if (blockIdx.x == 0) { cnt = ECNT; off = g_eoff; n = E_CAP; }
    else                 { cnt = NCNT; off = g_noff; n = N_CAP; }

    __shared__ int wsum[32];
    __shared__ int s_carry;
    int tid = threadIdx.x, lane = tid & 31, wid = tid >> 5;
    if (tid == 0) s_carry = 0;
    __syncthreads();

    for (int base = 0; base < n; base += SCAN_THREADS * 4) {
        int idx = base + tid * 4;
        int v0 = cnt[idx], v1 = cnt[idx + 1], v2 = cnt[idx + 2], v3 = cnt[idx + 3];
        int tsum = v0 + v1 + v2 + v3;
        int incl = tsum;
        #pragma unroll
        for (int s = 1; s < 32; s <<= 1) {
            int t = __shfl_up_sync(0xffffffffu, incl, s);
            if (lane >= s) incl += t;
        }
        if (lane == 31) wsum[wid] = incl;
        __syncthreads();
        if (wid == 0) {
            int w = wsum[lane];
            int wi = w;
            #pragma unroll
            for (int s = 1; s < 32; s <<= 1) {
                int t = __shfl_up_sync(0xffffffffu, wi, s);
                if (lane >= s) wi += t;
            }
            wsum[lane] = wi - w;  // exclusive warp prefix
        }
        __syncthreads();
        int ex = s_carry + wsum[wid] + incl - tsum;
        off[idx]     = ex;
        off[idx + 1] = ex + v0;
        off[idx + 2] = ex + v0 + v1;
        off[idx + 3] = ex + v0 + v1 + v2;
        __syncthreads();
        if (tid == SCAN_THREADS - 1) s_carry = ex + tsum;
        __syncthreads();
    }
    if (threadIdx.x == 0) off[n] = s_carry;
}

// ---------------- CSR build: bucket fill -------------------------------------
__global__ __launch_bounds__(256) void fill_kernel(const void* __restrict__ base, int nnz) {
    int i = blockIdx.x * blockDim.x + threadIdx.x;
    if (i >= nnz) return;
    int src, e;
    load_pair(base, i, nnz, src, e);
    int pe = g_eoff[e] + atomicAdd(&ECUR[e], 1);
    g_eidx[pe] = src;
    int pn = g_noff[src] + atomicAdd(&NCUR[src], 1);
    g_nidx[pn] = e;
}

// ---------------- GEMM: g_xnode = x @ W^T -----------------------------------
#define WT_STRIDE 132
#define GEMM_SMEM ((128 * WT_STRIDE + 64 * WT_STRIDE) * 4)

__global__ __launch_bounds__(256) void gemm_kernel(const float* __restrict__ x,
                                                   const float* __restrict__ W,
                                                   int N) {
    extern __shared__ float sm[];
    float* WT = sm;                       // [128][132], WT[k][j] = W[j][k]
    float* Xs = sm + 128 * WT_STRIDE;     // [64][132]

    int t = threadIdx.x;
    int row0 = blockIdx.x * 64;

    #pragma unroll
    for (int i = 0; i < 64; i++) {
        int idx = t + i * 256;
        int j = idx >> 7, k = idx & 127;
        WT[k * WT_STRIDE + j] = W[idx];
    }
    #pragma unroll
    for (int i = 0; i < 32; i++) {
        int idx = t + i * 256;
        int r = idx >> 7, k = idx & 127;
        int row = row0 + r;
        if (row >= N) row = N - 1;
        Xs[r * WT_STRIDE + k] = x[(size_t)row * D + k];
    }
    __syncthreads();

    int tx = t & 15, ty = t >> 4;
    int c0 = tx * 8, r0 = ty * 4;

    float acc[4][8];
    #pragma unroll
    for (int i = 0; i < 4; i++)
        #pragma unroll
        for (int j = 0; j < 8; j++) acc[i][j] = 0.f;

    #pragma unroll 4
    for (int k = 0; k < 128; k++) {
        float4 w0 = *(const float4*)(WT + k * WT_STRIDE + c0);
        float4 w1 = *(const float4*)(WT + k * WT_STRIDE + c0 + 4);
        #pragma unroll
        for (int i = 0; i < 4; i++) {
            float a = Xs[(r0 + i) * WT_STRIDE + k];
            acc[i][0] += a * w0.x; acc[i][1] += a * w0.y;
            acc[i][2] += a * w0.z; acc[i][3] += a * w0.w;
            acc[i][4] += a * w1.x; acc[i][5] += a * w1.y;
            acc[i][6] += a * w1.z; acc[i][7] += a * w1.w;
        }
    }

    #pragma unroll
    for (int i = 0; i < 4; i++) {
        int row = row0 + r0 + i;
        if (row < N) {
            *(float4*)(g_xnode + (size_t)row * D + c0) =
                make_float4(acc[i][0], acc[i][1], acc[i][2], acc[i][3]);
            *(float4*)(g_xnode + (size_t)row * D + c0 + 4) =
                make_float4(acc[i][4], acc[i][5], acc[i][6], acc[i][7]);
        }
    }
}

// ---------------- phase A: per-edge pull reduction ---------------------------
// One 128-thread block per edge; thread t owns feature t.
__global__ __launch_bounds__(128) void edge_agg_kernel() {
    int e = blockIdx.x;
    int beg = g_eoff[e], end = g_eoff[e + 1];
    int tid = threadIdx.x;

    float a0 = 0.f, a1 = 0.f, a2 = 0.f, a3 = 0.f;
    int j = beg;
    for (; j + 4 <= end; j += 4) {
        int s0 = g_eidx[j], s1 = g_eidx[j + 1], s2 = g_eidx[j + 2], s3 = g_eidx[j + 3];
        a0 += g_xnode[(size_t)s0 * D + tid];
        a1 += g_xnode[(size_t)s1 * D + tid];
        a2 += g_xnode[(size_t)s2 * D + tid];
        a3 += g_xnode[(size_t)s3 * D + tid];
    }
    for (; j < end; j++)
        a0 += g_xnode[(size_t)g_eidx[j] * D + tid];

    float inv = 1.0f / ((float)(end - beg) + EPS);
    g_heattr[(size_t)e * D + tid] = (a0 + a1 + a2 + a3) * inv;
}

// ---------------- phase B: per-node pull reduction + fused finalize ----------
// One warp per node; lane owns a float4 (4 features).
__global__ __launch_bounds__(256) void node_agg_kernel(const float* __restrict__ bias,
                                                       float* __restrict__ out,
                                                       int N) {
    int w = (blockIdx.x * blockDim.x + threadIdx.x) >> 5;
    if (w >= N) return;
    int lane = threadIdx.x & 31;
    int beg = g_noff[w], end = g_noff[w + 1];

    float4 a0 = make_float4(0.f, 0.f, 0.f, 0.f);
    float4 a1 = make_float4(0.f, 0.f, 0.f, 0.f);
    int j = beg;
    for (; j + 2 <= end; j += 2) {
        int e0 = g_nidx[j], e1 = g_nidx[j + 1];
        float4 v0 = *(const float4*)(g_heattr + (size_t)e0 * D + lane * 4);
        float4 v1 = *(const float4*)(g_heattr + (size_t)e1 * D + lane * 4);
        a0.x += v0.x; a0.y += v0.y; a0.z += v0.z; a0.w += v0.w;
        a1.x += v1.x; a1.y += v1.y; a1.z += v1.z; a1.w += v1.w;
    }
    if (j < end) {
        float4 v = *(const float4*)(g_heattr + (size_t)g_nidx[j] * D + lane * 4);
        a0.x += v.x; a0.y += v.y; a0.z += v.z; a0.w += v.w;
    }

    float s = 1.0f / ((float)(end - beg) + EPS);
    float4 xn = ((const float4*)g_xnode)[(size_t)w * 32 + lane];
    float4 b  = ((const float4*)bias)[lane];
    float4 o;
    o.x = (a0.x + a1.x) * s + xn.x + b.x;
    o.y = (a0.y + a1.y) * s + xn.y + b.y;
    o.z = (a0.z + a1.z) * s + xn.z + b.z;
    o.w = (a0.w + a1.w) * s + xn.w + b.w;
    ((float4*)out)[(size_t)w * 32 + lane] = o;
}

// ---------------- launch -----------------------------------------------------
extern "C" void kernel_launch(void* const* d_in, const int* in_sizes, int n_in,
                              void* d_out, int out_size) {
    const float* x    = (const float*)d_in[0];
    const void*  hidx = d_in[1];
    const float* W    = (const float*)d_in[2];
    const float* bias = (const float*)d_in[3];
    float* out = (float*)d_out;

    int N   = in_sizes[0] / D;
    int nnz = in_sizes[1] / 2;

    // counters: 2*(E_CAP+N_CAP) ints = 163840 -> 40960 int4
    zero_cnts_kernel<<<(2 * (E_CAP + N_CAP) / 4) / 256, 256>>>();
    detect_kernel<<<1, 32>>>((const int*)hidx);
    hist_kernel<<<(nnz + 255) / 256, 256>>>(hidx, nnz);
    scan_kernel<<<2, SCAN_THREADS>>>();
    fill_kernel<<<(nnz + 255) / 256, 256>>>(hidx, nnz);

    cudaFuncSetAttribute(gemm_kernel,
                         cudaFuncAttributeMaxDynamicSharedMemorySize, GEMM_SMEM);
    gemm_kernel<<<(N + 63) / 64, 256, GEMM_SMEM>>>(x, W, N);

    edge_agg_kernel<<<E_CAP, 128>>>();

    int warps = N;
    node_agg_kernel<<<(warps + 7) / 8, 256>>>(bias, out, N);
}

// round 3
// speedup vs baseline: 1.6705x; 1.3550x over previous
#include <cuda_runtime.h>
#include <cuda_bf16.h>
#include <stdint.h>

#define D 128
#define E_CAP 16384
#define N_CAP 65536
#define NNZ_CAP (1 << 20)
#define EPS 1e-8f
#define CHUNK 4096
#define NBLK_E (E_CAP / CHUNK)            // 4
#define NBLK_N (N_CAP / CHUNK)            // 16
#define NBLK_SCAN (NBLK_E + NBLK_N)       // 20

// ---------------- scratch (static device globals; no allocation) ------------
__device__ float    g_xnode[(size_t)N_CAP * D];      // fp32 (exact residual)
__device__ unsigned g_xnode_h[(size_t)N_CAP * 64];   // bf16x2 gather mirror
__device__ unsigned g_heattr_h[(size_t)E_CAP * 64];  // bf16x2 hyperedge attr
__device__ int g_eidx[NNZ_CAP];
__device__ int g_nidx[NNZ_CAP];
__device__ int g_eoff[E_CAP + 1];
__device__ int g_noff[N_CAP + 1];
__device__ int g_cnts[E_CAP + N_CAP];                // ecnt | ncnt (reused as cursors)
__device__ int g_bsum[NBLK_SCAN];
__device__ int g_is64;

#define ECNT (g_cnts)
#define NCNT (g_cnts + E_CAP)

// ---------------- zero counters ----------------------------------------------
__global__ void zero_cnts_kernel() {
    int i = blockIdx.x * blockDim.x + threadIdx.x;
    ((int4*)g_cnts)[i] = make_int4(0, 0, 0, 0);
}

// ---------------- index dtype detection (int64 vs int32) --------------------
__global__ void detect_kernel(const int* __restrict__ h) {
    if (threadIdx.x == 0)
        g_is64 = (h[1] == 0 && h[3] == 0 && h[5] == 0 && h[7] == 0) ? 1 : 0;
}

__device__ __forceinline__ void load_pair(const void* base, int i, int nnz,
                                          int& src, int& e) {
    if (g_is64) {
        const long long* p = (const long long*)base;
        src = (int)p[i];
        e   = (int)p[nnz + i];
    } else {
        const int* p = (const int*)base;
        src = p[i];
        e   = p[nnz + i];
    }
}

// ---------------- CSR build: histogram ---------------------------------------
__global__ __launch_bounds__(256) void hist_kernel(const void* __restrict__ base, int nnz) {
    int i = blockIdx.x * blockDim.x + threadIdx.x;
    if (i >= nnz) return;
    int src, e;
    load_pair(base, i, nnz, src, e);
    atomicAdd(&ECNT[e], 1);
    atomicAdd(&NCNT[src], 1);
}

// ---------------- CSR build: 2-level exclusive scan --------------------------
__global__ __launch_bounds__(1024) void scan_local_kernel() {
    int b = blockIdx.x;
    const int* cnt; int* off; int lo;
    if (b < NBLK_E) { cnt = ECNT; off = g_eoff; lo = b * CHUNK; }
    else            { cnt = NCNT; off = g_noff; lo = (b - NBLK_E) * CHUNK; }

    __shared__ int wsum[32];
    int tid = threadIdx.x, lane = tid & 31, wid = tid >> 5;
    int idx = lo + tid * 4;

    int4 v = *(const int4*)(cnt + idx);
    int tsum = v.x + v.y + v.z + v.w;
    int incl = tsum;
    #pragma unroll
    for (int s = 1; s < 32; s <<= 1) {
        int t = __shfl_up_sync(0xffffffffu, incl, s);
        if (lane >= s) incl += t;
    }
    if (lane == 31) wsum[wid] = incl;
    __syncthreads();
    if (wid == 0) {
        int w = wsum[lane];
        int wi = w;
        #pragma unroll
        for (int s = 1; s < 32; s <<= 1) {
            int t = __shfl_up_sync(0xffffffffu, wi, s);
            if (lane >= s) wi += t;
        }
        wsum[lane] = wi - w;
    }
    __syncthreads();
    int ex = wsum[wid] + incl - tsum;
    off[idx]     = ex;
    off[idx + 1] = ex + v.x;
    off[idx + 2] = ex + v.x + v.y;
    off[idx + 3] = ex + v.x + v.y + v.z;
    if (tid == 1023) g_bsum[b] = ex + tsum;
}

__global__ __launch_bounds__(1024) void scan_fixup_kernel() {
    int b = blockIdx.x;
    __shared__ int s_base;
    int tid = threadIdx.x;
    if (tid == 0) {
        int start = (b < NBLK_E) ? 0 : NBLK_E;
        int base = 0;
        for (int i = start; i < b; i++) base += g_bsum[i];
        s_base = base;
    }
    __syncthreads();
    int base = s_base;
    int* off; int lo;
    if (b < NBLK_E) { off = g_eoff; lo = b * CHUNK; }
    else            { off = g_noff; lo = (b - NBLK_E) * CHUNK; }
    int idx = lo + tid * 4;
    if (base) {
        int4 o = *(int4*)(off + idx);
        o.x += base; o.y += base; o.z += base; o.w += base;
        *(int4*)(off + idx) = o;
    }
    if (tid == 0) {
        if (b == NBLK_E - 1)    g_eoff[E_CAP] = base + g_bsum[b];
        if (b == NBLK_SCAN - 1) g_noff[N_CAP] = base + g_bsum[b];
    }
}

// ---------------- CSR build: bucket fill (countdown cursors) -----------------
__global__ __launch_bounds__(256) void fill_kernel(const void* __restrict__ base, int nnz) {
    int i = blockIdx.x * blockDim.x + threadIdx.x;
    if (i >= nnz) return;
    int src, e;
    load_pair(base, i, nnz, src, e);
    int pe = g_eoff[e] + atomicAdd(&ECNT[e], -1) - 1;
    g_eidx[pe] = src;
    int pn = g_noff[src] + atomicAdd(&NCNT[src], -1) - 1;
    g_nidx[pn] = e;
}

// ---------------- GEMM: g_xnode = x @ W^T (packed f32x2 FMA) -----------------
#define WT_STRIDE 132
#define GEMM_SMEM ((128 * WT_STRIDE + 64 * WT_STRIDE) * 4)

__device__ __forceinline__ unsigned long long fma2(unsigned long long a,
                                                   unsigned long long b,
                                                   unsigned long long c) {
    unsigned long long d;
    asm("fma.rn.f32x2 %0, %1, %2, %3;" : "=l"(d) : "l"(a), "l"(b), "l"(c));
    return d;
}

__global__ __launch_bounds__(256) void gemm_kernel(const float* __restrict__ x,
                                                   const float* __restrict__ W,
                                                   int N) {
    extern __shared__ float sm[];
    float* WT = sm;                       // [128][132], WT[k][j] = W[j][k]
    float* Xs = sm + 128 * WT_STRIDE;     // [64][132]

    int t = threadIdx.x;
    int row0 = blockIdx.x * 64;

    #pragma unroll
    for (int i = 0; i < 64; i++) {
        int idx = t + i * 256;
        int j = idx >> 7, k = idx & 127;
        WT[k * WT_STRIDE + j] = W[idx];
    }
    #pragma unroll
    for (int i = 0; i < 32; i++) {
        int idx = t + i * 256;
        int r = idx >> 7, k = idx & 127;
        int row = row0 + r;
        if (row >= N) row = N - 1;
        Xs[r * WT_STRIDE + k] = x[(size_t)row * D + k];
    }
    __syncthreads();

    int tx = t & 15, ty = t >> 4;
    int c0 = tx * 8, r0 = ty * 4;

    unsigned long long acc[4][4];
    #pragma unroll
    for (int i = 0; i < 4; i++)
        #pragma unroll
        for (int j = 0; j < 4; j++) acc[i][j] = 0ull;

    #pragma unroll 4
    for (int k = 0; k < 128; k++) {
        ulonglong2 wa = *(const ulonglong2*)(WT + k * WT_STRIDE + c0);
        ulonglong2 wb = *(const ulonglong2*)(WT + k * WT_STRIDE + c0 + 4);
        #pragma unroll
        for (int i = 0; i < 4; i++) {
            unsigned au = __float_as_uint(Xs[(r0 + i) * WT_STRIDE + k]);
            unsigned long long aa;
            asm("mov.b64 %0, {%1, %1};" : "=l"(aa) : "r"(au));
            acc[i][0] = fma2(aa, wa.x, acc[i][0]);
            acc[i][1] = fma2(aa, wa.y, acc[i][1]);
            acc[i][2] = fma2(aa, wb.x, acc[i][2]);
            acc[i][3] = fma2(aa, wb.y, acc[i][3]);
        }
    }

    #pragma unroll
    for (int i = 0; i < 4; i++) {
        int row = row0 + r0 + i;
        if (row < N) {
            // fp32 store (packed pairs are exactly two consecutive floats)
            ulonglong2 o0; o0.x = acc[i][0]; o0.y = acc[i][1];
            ulonglong2 o1; o1.x = acc[i][2]; o1.y = acc[i][3];
            *(ulonglong2*)(g_xnode + (size_t)row * D + c0)     = o0;
            *(ulonglong2*)(g_xnode + (size_t)row * D + c0 + 4) = o1;
            // bf16 mirror
            uint4 h;
            #pragma unroll
            for (int j = 0; j < 4; j++) {
                unsigned lo, hi;
                asm("mov.b64 {%0, %1}, %2;" : "=r"(lo), "=r"(hi) : "l"(acc[i][j]));
                unsigned r2;
                asm("cvt.rn.bf16x2.f32 %0, %1, %2;" : "=r"(r2)
                    : "f"(__uint_as_float(hi)), "f"(__uint_as_float(lo)));
                ((unsigned*)&h)[j] = r2;
            }
            *(uint4*)(g_xnode_h + (size_t)row * 64 + tx * 4) = h;
        }
    }
}

// ---------------- phase A: per-edge pull reduction (bf16 gather) -------------
// 128-thread block handles 2 edges; 64 threads/edge, thread owns 2 features.
__global__ __launch_bounds__(128) void edge_agg_kernel() {
    int half = threadIdx.x >> 6;
    int t = threadIdx.x & 63;
    int e = blockIdx.x * 2 + half;
    int beg = g_eoff[e], end = g_eoff[e + 1];
    if (beg == end) return;

    float s0a = 0.f, s1a = 0.f, s0b = 0.f, s1b = 0.f;
    int j = beg;
    for (; j + 2 <= end; j += 2) {
        int n0 = g_eidx[j], n1 = g_eidx[j + 1];
        unsigned u0 = g_xnode_h[(size_t)n0 * 64 + t];
        unsigned u1 = g_xnode_h[(size_t)n1 * 64 + t];
        s0a += __uint_as_float(u0 << 16);
        s1a += __uint_as_float(u0 & 0xffff0000u);
        s0b += __uint_as_float(u1 << 16);
        s1b += __uint_as_float(u1 & 0xffff0000u);
    }
    if (j < end) {
        unsigned u = g_xnode_h[(size_t)g_eidx[j] * 64 + t];
        s0a += __uint_as_float(u << 16);
        s1a += __uint_as_float(u & 0xffff0000u);
    }
    float inv = 1.0f / ((float)(end - beg) + EPS);
    float f0 = (s0a + s0b) * inv;
    float f1 = (s1a + s1b) * inv;
    unsigned r;
    asm("cvt.rn.bf16x2.f32 %0, %1, %2;" : "=r"(r) : "f"(f1), "f"(f0));
    g_heattr_h[(size_t)e * 64 + t] = r;
}

// ---------------- phase B: per-node pull + fused finalize (bf16 gather) ------
__global__ __launch_bounds__(256) void node_agg_kernel(const float* __restrict__ bias,
                                                       float* __restrict__ out,
                                                       int N) {
    int w = (blockIdx.x * blockDim.x + threadIdx.x) >> 5;
    if (w >= N) return;
    int lane = threadIdx.x & 31;
    int beg = g_noff[w], end = g_noff[w + 1];

    float4 a = make_float4(0.f, 0.f, 0.f, 0.f);
    float4 a2 = make_float4(0.f, 0.f, 0.f, 0.f);
    int j = beg;
    for (; j + 2 <= end; j += 2) {
        int e0 = g_nidx[j], e1 = g_nidx[j + 1];
        uint2 u0 = *(const uint2*)(g_heattr_h + (size_t)e0 * 64 + lane * 2);
        uint2 u1 = *(const uint2*)(g_heattr_h + (size_t)e1 * 64 + lane * 2);
        a.x  += __uint_as_float(u0.x << 16);
        a.y  += __uint_as_float(u0.x & 0xffff0000u);
        a.z  += __uint_as_float(u0.y << 16);
        a.w  += __uint_as_float(u0.y & 0xffff0000u);
        a2.x += __uint_as_float(u1.x << 16);
        a2.y += __uint_as_float(u1.x & 0xffff0000u);
        a2.z += __uint_as_float(u1.y << 16);
        a2.w += __uint_as_float(u1.y & 0xffff0000u);
    }
    if (j < end) {
        uint2 u = *(const uint2*)(g_heattr_h + (size_t)g_nidx[j] * 64 + lane * 2);
        a.x += __uint_as_float(u.x << 16);
        a.y += __uint_as_float(u.x & 0xffff0000u);
        a.z += __uint_as_float(u.y << 16);
        a.w += __uint_as_float(u.y & 0xffff0000u);
    }

    float s = 1.0f / ((float)(end - beg) + EPS);
    float4 xn = ((const float4*)g_xnode)[(size_t)w * 32 + lane];
    float4 b  = ((const float4*)bias)[lane];
    float4 o;
    o.x = (a.x + a2.x) * s + xn.x + b.x;
    o.y = (a.y + a2.y) * s + xn.y + b.y;
    o.z = (a.z + a2.z) * s + xn.z + b.z;
    o.w = (a.w + a2.w) * s + xn.w + b.w;
    ((float4*)out)[(size_t)w * 32 + lane] = o;
}

// ---------------- launch -----------------------------------------------------
extern "C" void kernel_launch(void* const* d_in, const int* in_sizes, int n_in,
                              void* d_out, int out_size) {
    const float* x    = (const float*)d_in[0];
    const void*  hidx = d_in[1];
    const float* W    = (const float*)d_in[2];
    const float* bias = (const float*)d_in[3];
    float* out = (float*)d_out;

    int N   = in_sizes[0] / D;
    int nnz = in_sizes[1] / 2;

    static cudaStream_t s2 = 0;
    static cudaEvent_t evA = 0, evB = 0;
    if (!s2) {
        cudaStreamCreateWithFlags(&s2, cudaStreamNonBlocking);
        cudaEventCreateWithFlags(&evA, cudaEventDisableTiming);
        cudaEventCreateWithFlags(&evB, cudaEventDisableTiming);
        cudaFuncSetAttribute(gemm_kernel,
                             cudaFuncAttributeMaxDynamicSharedMemorySize, GEMM_SMEM);
    }

    // fork: GEMM (+bf16 mirror) runs concurrently with CSR build
    cudaEventRecord(evA, 0);
    cudaStreamWaitEvent(s2, evA, 0);
    gemm_kernel<<<(N + 63) / 64, 256, GEMM_SMEM, s2>>>(x, W, N);

    // CSR chain on capture stream
    zero_cnts_kernel<<<(E_CAP + N_CAP) / 4 / 256, 256>>>();
    detect_kernel<<<1, 32>>>((const int*)hidx);
    hist_kernel<<<(nnz + 255) / 256, 256>>>(hidx, nnz);
    scan_local_kernel<<<NBLK_SCAN, 1024>>>();
    scan_fixup_kernel<<<NBLK_SCAN, 1024>>>();
    fill_kernel<<<(nnz + 255) / 256, 256>>>(hidx, nnz);

    // join
    cudaEventRecord(evB, s2);
    cudaStreamWaitEvent(0, evB, 0);

    edge_agg_kernel<<<E_CAP / 2, 128>>>();
    node_agg_kernel<<<(N + 7) / 8, 256>>>(bias, out, N);
}